// round 16
// baseline (speedup 1.0000x reference)
#include <cuda_runtime.h>
#include <cuda_bf16.h>
#include <cstdint>

// Problem constants
#define T_LEN  4096
#define NB     32
#define NU     64
#define NY     64
#define NH     256
#define HH     128
#define CH2    32            // sub-chunk length
#define NC2    128           // T / CH2
#define NROWS  (T_LEN * NB)

// ---------------- scratch globals -------------------------------------------
__device__ float2 g_X2[T_LEN * NB * HH];      // local-scan (zr,zi), 128 MiB
__device__ float2 g_s[NC2 * NB * HH];         // per-subchunk local end states
__device__ float2 g_S[NC2 * NB * HH];         // carry entering each subchunk
__device__ float2 g_P2[CH2 * HH];             // lambda^(k+1), k<32
__device__ float2 g_lam[HH];
__device__ float2 g_lamL[HH];                 // lambda^32
__device__ float  g_x0[NB * NH];
// B packed in 2 channel-pair halves: half n: [r=128][136] bf16 (hi|lo)
__device__ __align__(16) uint8_t g_B1h[2 * 128 * 136 * 2];   // 69632
// W packed in 4 K-quarters: quarter q: [y=64][136] bf16
__device__ __align__(16) uint8_t g_W4p[4 * 64 * 136 * 2];    // 69632

// ---------------- helpers ----------------------------------------------------
__device__ __forceinline__ uint32_t smem_u32(const void* p) {
    uint32_t a;
    asm("{ .reg .u64 t; cvta.to.shared.u64 t, %1; cvt.u32.u64 %0, t; }" : "=r"(a) : "l"(p));
    return a;
}
__device__ __forceinline__ void ldsm4(uint32_t* r, uint32_t addr) {
    asm volatile("ldmatrix.sync.aligned.m8n8.x4.shared.b16 {%0,%1,%2,%3}, [%4];"
                 : "=r"(r[0]), "=r"(r[1]), "=r"(r[2]), "=r"(r[3]) : "r"(addr));
}
__device__ __forceinline__ void mma_bf16(float* d, const uint32_t* a,
                                         uint32_t b0, uint32_t b1) {
    asm volatile("mma.sync.aligned.m16n8k16.row.col.f32.bf16.bf16.f32 "
                 "{%0,%1,%2,%3}, {%4,%5,%6,%7}, {%8,%9}, {%0,%1,%2,%3};"
                 : "+f"(d[0]), "+f"(d[1]), "+f"(d[2]), "+f"(d[3])
                 : "r"(a[0]), "r"(a[1]), "r"(a[2]), "r"(a[3]), "r"(b0), "r"(b1));
}
__device__ __forceinline__ void cp16(uint32_t dst, const void* src) {
    asm volatile("cp.async.cg.shared.global [%0], [%1], 16;" :: "r"(dst), "l"(src));
}
#define CP_COMMIT() asm volatile("cp.async.commit_group;")
#define CP_WAIT0()  asm volatile("cp.async.wait_group 0;")
__device__ __forceinline__ void split_bf16(float x, __nv_bfloat16& hi, __nv_bfloat16& lo) {
    hi = __float2bfloat16(x);
    lo = __float2bfloat16(x - __bfloat162float(hi));
}
// FAST split: two floats -> packed bf16x2 hi word + lo word (a low, b high).
__device__ __forceinline__ void split2(float a, float b, uint32_t& hw, uint32_t& lw) {
    asm("cvt.rn.bf16x2.f32 %0, %1, %2;" : "=r"(hw) : "f"(b), "f"(a));  // low=a, high=b
    float fa = __uint_as_float(hw << 16);
    float fb = __uint_as_float(hw & 0xffff0000u);
    asm("cvt.rn.bf16x2.f32 %0, %1, %2;" : "=r"(lw) : "f"(b - fb), "f"(a - fa));
}

// ---------------- K_init: lambda/P/x0/pack merged (grid 41 x 256) ------------
__global__ void k_init(const float* __restrict__ y0,
                       const float* __restrict__ lre,
                       const float* __restrict__ lim,
                       const float* __restrict__ B,
                       const float* __restrict__ Wy2x,
                       const float* __restrict__ by2x,
                       const float* __restrict__ Wx2y) {
    int blk = blockIdx.x, tid = threadIdx.x;
    if (blk == 0) {
        if (tid < HH) {
            int h = tid;
            float ar = fabsf(lre[h]);
            float th = 1.5707963267948966f * lim[h];
            float r  = expf(-ar);
            float sn, cs;
            sincosf(th, &sn, &cs);
            g_lam[h] = make_float2(r * cs, r * sn);
            float rL = expf(-32.0f * ar);
            float sL, cL;
            sincosf(32.0f * th, &sL, &cL);
            g_lamL[h] = make_float2(rL * cL, rL * sL);
            #pragma unroll 4
            for (int k = 0; k < CH2; k++) {
                float kk  = (float)(k + 1);
                float rho = expf(-kk * ar);
                float s2, c2;
                sincosf(kk * th, &s2, &c2);
                g_P2[k * HH + h] = make_float2(rho * c2, rho * s2);
            }
        }
    } else if (blk <= 32) {
        __shared__ float ys[NY];
        int b = blk - 1;
        if (tid < NY) ys[tid] = y0[b * NY + tid];
        __syncthreads();
        int j = tid;
        float acc = by2x[j];
        #pragma unroll
        for (int y = 0; y < NY; y++) acc = fmaf(Wy2x[j * NY + y], ys[y], acc);
        g_x0[b * NH + j] = acc;
    } else if (blk <= 36) {
        __nv_bfloat16* bp = (__nv_bfloat16*)g_B1h;
        int base = (blk - 33) * 4096;
        for (int q = tid; q < 4096; q += 256) {
            int i = base + q;
            int h = i >> 6, u = i & 63;
            int hp = (h < HH) ? h : (h - HH);
            int n  = hp >> 6;
            int r  = (hp & 63) + ((h < HH) ? 0 : 64);
            __nv_bfloat16 hi, lo;
            split_bf16(B[i], hi, lo);
            __nv_bfloat16* dst = bp + n * (128 * 136);
            dst[r * 136 + u]      = hi;
            dst[r * 136 + 64 + u] = lo;
        }
    } else {
        // W quarter pack
        __nv_bfloat16* wp = (__nv_bfloat16*)g_W4p;
        int base = (blk - 37) * 4096;
        for (int qq = tid; qq < 4096; qq += 256) {
            int i = base + qq;
            int y = i >> 8, k = i & 255;
            __nv_bfloat16 hi, lo;
            split_bf16(Wx2y[i], hi, lo);
            int hp  = (k < HH) ? k : (k - HH);
            int q   = hp >> 5;
            int col = (hp & 31) + ((k < HH) ? 0 : 32);
            __nv_bfloat16* dst = wp + q * (64 * 136) + y * 136;
            dst[col]      = hi;
            dst[col + 64] = lo;
        }
    }
}

// ---------------- K_A: HMMA Bu GEMM (N-half) + 32-step scan ------------------
// grid (64, 32, 2): tile c (64 rows), batch b, channel-half n. 256 threads.
#define FA_A1 0
#define FA_B1 17408
#define FA_TOTAL 52224
#define XPITCH 65

__global__ __launch_bounds__(256, 3)
void k_fusedA(const float* __restrict__ U) {
    extern __shared__ char smem[];
    uint32_t sb = smem_u32(smem);
    int tid = threadIdx.x, wid = tid >> 5, lane = tid & 31;
    int c = blockIdx.x, b = blockIdx.y, n = blockIdx.z;
    int t0 = c * 64;

    // cp.async stage of B half (34816 B)
    {
        const char* src = (const char*)g_B1h + n * 34816;
        for (int i = tid; i < 2176; i += 256)
            cp16(sb + FA_B1 + i * 16, src + i * 16);
        CP_COMMIT();
    }
    // convert U tile -> A1 [tl=64][136] (hi | lo), vectorized float4 -> fast split2
    {
        __nv_bfloat16* ap = (__nv_bfloat16*)(smem + FA_A1);
        #pragma unroll
        for (int i = tid; i < 64 * 16; i += 256) {
            int tl = i >> 4, u4 = (i & 15) * 4;
            float4 v = *(const float4*)(U + ((size_t)(t0 + tl) * NB + b) * NU + u4);
            uint32_t hA, lA, hB, lB;
            split2(v.x, v.y, hA, lA);
            split2(v.z, v.w, hB, lB);
            *(uint2*)(ap + tl * 136 + u4)      = make_uint2(hA, hB);
            *(uint2*)(ap + tl * 136 + 64 + u4) = make_uint2(lA, lB);
        }
    }
    CP_WAIT0();
    __syncthreads();

    // GEMM: M=64, N=128(local), K=64 x 3 terms; warp = 16M x 64N.
    // Fragment-sharing loop order (R12 proven form).
    int wm = (wid & 3) * 16;
    int wn = (wid >> 2) * 64;
    int lr = lane & 15, lc = lane >> 4;
    uint32_t a_base = sb + FA_A1 + (uint32_t)(wm + lr) * 272u + (uint32_t)lc * 16u;
    uint32_t b_base = sb + FA_B1 + (uint32_t)(wn + lr) * 272u + (uint32_t)lc * 16u;

    float d[8][4];
    #pragma unroll
    for (int x = 0; x < 8; x++)
        #pragma unroll
        for (int q = 0; q < 4; q++) d[x][q] = 0.f;

    #pragma unroll
    for (int ks = 0; ks < 4; ks++) {
        uint32_t ah[4], al[4];
        ldsm4(ah, a_base + ks * 32u);           // A hi (cols 0..63)
        ldsm4(al, a_base + 128u + ks * 32u);    // A lo (cols 64..127)
        #pragma unroll
        for (int nt = 0; nt < 4; nt++) {
            uint32_t bh[4], bl[4];
            uint32_t boffn = ks * 32u + (uint32_t)nt * (16u * 272u);
            ldsm4(bh, b_base + boffn);          // B hi
            ldsm4(bl, b_base + 128u + boffn);   // B lo
            mma_bf16(d[2 * nt],     ah, bh[0], bh[2]);
            mma_bf16(d[2 * nt + 1], ah, bh[1], bh[3]);
            mma_bf16(d[2 * nt],     al, bh[0], bh[2]);
            mma_bf16(d[2 * nt + 1], al, bh[1], bh[3]);
            mma_bf16(d[2 * nt],     ah, bl[0], bl[2]);
            mma_bf16(d[2 * nt + 1], ah, bl[1], bl[3]);
        }
    }
    __syncthreads();   // done with A1/B1; reuse as Xs

    // transpose into Xs[hl=128][r=64 + pad]
    float* Xs = (float*)smem;
    {
        int g = lane >> 2, tq = lane & 3;
        #pragma unroll
        for (int dm = 0; dm < 8; dm++) {
            int hl = wn + dm * 8 + tq * 2;
            int r0 = wm + g;
            Xs[hl * XPITCH + r0]           = d[dm][0];
            Xs[(hl + 1) * XPITCH + r0]     = d[dm][1];
            Xs[hl * XPITCH + r0 + 8]       = d[dm][2];
            Xs[(hl + 1) * XPITCH + r0 + 8] = d[dm][3];
        }
    }
    __syncthreads();

    // 32-step scan: thread = (hp_loc, subchunk)
    if (tid < 128) {
        int hp = tid & 63, sc = tid >> 6;
        int hg = n * 64 + hp;
        float2 lam = g_lam[hg];
        const float* rowR = Xs + hp * XPITCH + sc * 32;
        const float* rowI = Xs + (64 + hp) * XPITCH + sc * 32;
        float zr = 0.f, zi = 0.f;
        #pragma unroll 4
        for (int k = 0; k < CH2; k++) {
            float a  = rowR[k];
            float bi = rowI[k];
            float nzr = fmaf(lam.x, zr, fmaf(-lam.y, zi, a));
            float nzi = fmaf(lam.y, zr, fmaf( lam.x, zi, bi));
            zr = nzr; zi = nzi;
            g_X2[((size_t)(t0 + sc * 32 + k) * NB + b) * HH + hg] = make_float2(zr, zi);
        }
        g_s[((c * 2 + sc) * NB + b) * HH + hg] = make_float2(zr, zi);
    }
}

// ---------------- K3: combine across 128 subchunks (prefetched) --------------
__global__ void k_combine() {
    int b = blockIdx.x;
    int h = threadIdx.x;
    float2 lamL = g_lamL[h];
    float Sr = g_x0[b * NH + h];
    float Si = g_x0[b * NH + HH + h];
    float2 buf[8];
    #pragma unroll
    for (int j = 0; j < 8; j++) buf[j] = g_s[(j * NB + b) * HH + h];
    #pragma unroll 1
    for (int c0 = 0; c0 < NC2; c0 += 8) {
        float2 nxt[8];
        if (c0 + 8 < NC2) {
            #pragma unroll
            for (int j = 0; j < 8; j++) nxt[j] = g_s[((c0 + 8 + j) * NB + b) * HH + h];
        }
        #pragma unroll
        for (int j = 0; j < 8; j++) {
            g_S[((c0 + j) * NB + b) * HH + h] = make_float2(Sr, Si);
            float2 s = buf[j];
            float nr = fmaf(lamL.x, Sr, fmaf(-lamL.y, Si, s.x));
            float ni = fmaf(lamL.y, Sr, fmaf( lamL.x, Si, s.y));
            Sr = nr; Si = ni;
        }
        #pragma unroll
        for (int j = 0; j < 8; j++) buf[j] = nxt[j];
    }
}

// ---------------- K_C: producer/consumer output GEMM -------------------------
// grid 2048 x 64 rows, 256 threads.
// warps 0-3: consumers, 2M x 2N tiling (32Mx32N tile each, term-outer order).
// warps 4-7: producers. K split in 4 quarters, double-buffered A2 + W.
#define OC_WBUF(i) (1024u + (uint32_t)(i) * 17408u)
#define OC_ABUF(i) (35840u + (uint32_t)(i) * 17408u)
#define OC_TOTAL 70656

__device__ __forceinline__ void oc_build_quarter(
        char* smem, int q, int abuf, int row0, int c2, int tl0, int ptid) {
    __nv_bfloat16* ap = (__nv_bfloat16*)(smem + OC_ABUF(abuf));
    #pragma unroll
    for (int u = 0; u < 4; u++) {
        int idx = u * 128 + ptid;      // 0..511
        int rp  = idx >> 4;            // row-pair 0..31 (b = rp)
        int jp  = (idx & 15) * 2;      // even local channel
        int hp  = q * 32 + jp;
        int R   = row0 + rp;
        float4 Sv  = *(const float4*)&g_S[(c2 * NB + rp) * HH + hp];
        float4 x0v = *(const float4*)&g_X2[(size_t)R * HH + hp];
        float4 x1v = *(const float4*)&g_X2[(size_t)(R + 32) * HH + hp];
        float4 P0  = *(const float4*)&g_P2[tl0 * HH + hp];
        float4 P1  = *(const float4*)&g_P2[(tl0 + 1) * HH + hp];
        float xr0a = fmaf(P0.x, Sv.x, fmaf(-P0.y, Sv.y, x0v.x));
        float xi0a = fmaf(P0.y, Sv.x, fmaf( P0.x, Sv.y, x0v.y));
        float xr0b = fmaf(P0.z, Sv.z, fmaf(-P0.w, Sv.w, x0v.z));
        float xi0b = fmaf(P0.w, Sv.z, fmaf( P0.z, Sv.w, x0v.w));
        float xr1a = fmaf(P1.x, Sv.x, fmaf(-P1.y, Sv.y, x1v.x));
        float xi1a = fmaf(P1.y, Sv.x, fmaf( P1.x, Sv.y, x1v.y));
        float xr1b = fmaf(P1.z, Sv.z, fmaf(-P1.w, Sv.w, x1v.z));
        float xi1b = fmaf(P1.w, Sv.z, fmaf( P1.z, Sv.w, x1v.w));
        uint32_t hR0, lR0, hI0, lI0, hR1, lR1, hI1, lI1;
        split2(xr0a, xr0b, hR0, lR0);
        split2(xi0a, xi0b, hI0, lI0);
        split2(xr1a, xr1b, hR1, lR1);
        split2(xi1a, xi1b, hI1, lI1);
        int wj = jp >> 1;              // word col 0..15 (row pitch 68 words)
        uint32_t* wA = (uint32_t*)(ap + (size_t)rp * 136);
        wA[wj]      = hR0;             // hi real  (cols 0..31)
        wA[16 + wj] = hI0;             // hi imag  (cols 32..63)
        wA[32 + wj] = lR0;             // lo real  (cols 64..95)
        wA[48 + wj] = lI0;             // lo imag  (cols 96..127)
        uint32_t* wB = (uint32_t*)(ap + (size_t)(rp + 32) * 136);
        wB[wj]      = hR1;
        wB[16 + wj] = hI1;
        wB[32 + wj] = lR1;
        wB[48 + wj] = lI1;
    }
}

__global__ __launch_bounds__(256, 3)
void k_outC(const float* __restrict__ bias, float* __restrict__ Y) {
    extern __shared__ char smem[];
    uint32_t sb = smem_u32(smem);
    int tid = threadIdx.x, wid = tid >> 5, lane = tid & 31;
    int row0 = blockIdx.x * 64;
    int t_base = blockIdx.x * 2;
    int c2 = t_base >> 5;
    int tl0 = t_base & 31;
    int lr = lane & 15, lc = lane >> 4;

    if (tid < NY) ((float*)smem)[tid] = bias[tid];

    // consumer tiling: 2M x 2N (32 rows x 32 cols per warp)
    int wmC = (wid & 1) * 32;
    int wnC = ((wid >> 1) & 1) * 32;

    float d[2][4][4];
    #pragma unroll
    for (int mt = 0; mt < 2; mt++)
        #pragma unroll
        for (int j = 0; j < 4; j++)
            #pragma unroll
            for (int qq = 0; qq < 4; qq++) d[mt][j][qq] = 0.f;

    // prologue: producers stage quarter 0 (W + A2)
    if (wid >= 4) {
        int ptid = tid - 128;
        const char* src = (const char*)g_W4p;
        for (int i = ptid; i < 1088; i += 128)
            cp16(sb + OC_WBUF(0) + i * 16, src + i * 16);
        CP_COMMIT();
        oc_build_quarter(smem, 0, 0, row0, c2, tl0, ptid);
        CP_WAIT0();
    }
    __syncthreads();

    #pragma unroll 1
    for (int q = 0; q < 4; q++) {
        int buf = q & 1, nbuf = buf ^ 1;
        if (wid >= 4) {
            if (q < 3) {
                int ptid = tid - 128;
                const char* src = (const char*)g_W4p + (q + 1) * 17408;
                for (int i = ptid; i < 1088; i += 128)
                    cp16(sb + OC_WBUF(nbuf) + i * 16, src + i * 16);
                CP_COMMIT();
                oc_build_quarter(smem, q + 1, nbuf, row0, c2, tl0, tid - 128);
                CP_WAIT0();
            }
        } else {
            // consumer GEMM on quarter q: 32M x 32N per warp, K=64 x 3 terms,
            // term-outer order (proven best), 2 A + 2 B ldsm per (t,ks).
            uint32_t a_base = sb + OC_ABUF(buf) + (uint32_t)(wmC + lr) * 272u
                            + (uint32_t)lc * 16u;
            uint32_t b_base = sb + OC_WBUF(buf) + (uint32_t)(wnC + lr) * 272u
                            + (uint32_t)lc * 16u;
            #pragma unroll
            for (int t = 0; t < 3; t++) {
                const uint32_t aoff = (t == 1) ? 128u : 0u;   // A-lo at +64 cols
                const uint32_t boff = (t == 2) ? 128u : 0u;   // W-lo at +64 cols
                #pragma unroll
                for (int ks = 0; ks < 4; ks++) {
                    uint32_t a0[4], a1[4], b0[4], b1[4];
                    ldsm4(a0, a_base + aoff + ks * 32u);
                    ldsm4(a1, a_base + aoff + ks * 32u + 16u * 272u);
                    ldsm4(b0, b_base + boff + ks * 32u);
                    ldsm4(b1, b_base + boff + ks * 32u + 16u * 272u);
                    mma_bf16(d[0][0], a0, b0[0], b0[2]);
                    mma_bf16(d[0][1], a0, b0[1], b0[3]);
                    mma_bf16(d[0][2], a0, b1[0], b1[2]);
                    mma_bf16(d[0][3], a0, b1[1], b1[3]);
                    mma_bf16(d[1][0], a1, b0[0], b0[2]);
                    mma_bf16(d[1][1], a1, b0[1], b0[3]);
                    mma_bf16(d[1][2], a1, b1[0], b1[2]);
                    mma_bf16(d[1][3], a1, b1[1], b1[3]);
                }
            }
        }
        __syncthreads();
    }

    // epilogue: consumers add bias + store
    if (wid < 4) {
        const float* bs = (const float*)smem;
        int g = lane >> 2, tq = lane & 3;
        #pragma unroll
        for (int mt = 0; mt < 2; mt++) {
            int RA = row0 + wmC + mt * 16 + g;
            int RB = RA + 8;
            #pragma unroll
            for (int j = 0; j < 4; j++) {
                int col = wnC + j * 8 + tq * 2;
                float b0 = bs[col], b1 = bs[col + 1];
                *(float2*)(Y + (size_t)RA * NY + col) =
                    make_float2(d[mt][j][0] + b0, d[mt][j][1] + b1);
                *(float2*)(Y + (size_t)RB * NY + col) =
                    make_float2(d[mt][j][2] + b0, d[mt][j][3] + b1);
            }
        }
    }
}

// ---------------- launch ----------------------------------------------------
extern "C" void kernel_launch(void* const* d_in, const int* in_sizes, int n_in,
                              void* d_out, int out_size) {
    const float* y0   = (const float*)d_in[0];
    const float* U    = (const float*)d_in[1];
    const float* lre  = (const float*)d_in[2];
    const float* lim  = (const float*)d_in[3];
    const float* B    = (const float*)d_in[4];
    const float* Wy2x = (const float*)d_in[5];
    const float* by2x = (const float*)d_in[6];
    const float* Wx2y = (const float*)d_in[7];
    const float* bx2y = (const float*)d_in[8];
    float* Y = (float*)d_out;

    k_init<<<41, 256>>>(y0, lre, lim, B, Wy2x, by2x, Wx2y);

    cudaFuncSetAttribute(k_fusedA, cudaFuncAttributeMaxDynamicSharedMemorySize, FA_TOTAL);
    k_fusedA<<<dim3(64, NB, 2), 256, FA_TOTAL>>>(U);

    k_combine<<<NB, 128>>>();

    cudaFuncSetAttribute(k_outC, cudaFuncAttributeMaxDynamicSharedMemorySize, OC_TOTAL);
    k_outC<<<NROWS / 64, 256, OC_TOTAL>>>(bx2y, Y);
}

// round 17
// speedup vs baseline: 1.3798x; 1.3798x over previous
#include <cuda_runtime.h>
#include <cuda_bf16.h>
#include <cstdint>

// Problem constants
#define T_LEN  4096
#define NB     32
#define NU     64
#define NY     64
#define NH     256
#define HH     128
#define CH2    32            // sub-chunk length
#define NC2    128           // T / CH2
#define NROWS  (T_LEN * NB)

// ---------------- scratch globals -------------------------------------------
__device__ float2 g_X2[T_LEN * NB * HH];      // local-scan (zr,zi), 128 MiB
__device__ float2 g_s[NC2 * NB * HH];         // per-subchunk local end states
__device__ float2 g_S[NC2 * NB * HH];         // carry entering each subchunk
__device__ float2 g_P2[CH2 * HH];             // lambda^(k+1), k<32
__device__ float2 g_lam[HH];
__device__ float2 g_lamL[HH];                 // lambda^32
__device__ float  g_x0[NB * NH];
// B packed in 2 channel-pair halves: half n: [r=128][136] bf16 (hi|lo)
__device__ __align__(16) uint8_t g_B1h[2 * 128 * 136 * 2];   // 69632
// W packed in 4 K-quarters: quarter q: [y=64][136] bf16
__device__ __align__(16) uint8_t g_W4p[4 * 64 * 136 * 2];    // 69632

// ---------------- helpers ----------------------------------------------------
__device__ __forceinline__ uint32_t smem_u32(const void* p) {
    uint32_t a;
    asm("{ .reg .u64 t; cvta.to.shared.u64 t, %1; cvt.u32.u64 %0, t; }" : "=r"(a) : "l"(p));
    return a;
}
__device__ __forceinline__ void ldsm4(uint32_t* r, uint32_t addr) {
    asm volatile("ldmatrix.sync.aligned.m8n8.x4.shared.b16 {%0,%1,%2,%3}, [%4];"
                 : "=r"(r[0]), "=r"(r[1]), "=r"(r[2]), "=r"(r[3]) : "r"(addr));
}
__device__ __forceinline__ void mma_bf16(float* d, const uint32_t* a,
                                         uint32_t b0, uint32_t b1) {
    asm volatile("mma.sync.aligned.m16n8k16.row.col.f32.bf16.bf16.f32 "
                 "{%0,%1,%2,%3}, {%4,%5,%6,%7}, {%8,%9}, {%0,%1,%2,%3};"
                 : "+f"(d[0]), "+f"(d[1]), "+f"(d[2]), "+f"(d[3])
                 : "r"(a[0]), "r"(a[1]), "r"(a[2]), "r"(a[3]), "r"(b0), "r"(b1));
}
__device__ __forceinline__ void cp16(uint32_t dst, const void* src) {
    asm volatile("cp.async.cg.shared.global [%0], [%1], 16;" :: "r"(dst), "l"(src));
}
#define CP_COMMIT() asm volatile("cp.async.commit_group;")
#define CP_WAIT0()  asm volatile("cp.async.wait_group 0;")
__device__ __forceinline__ void split_bf16(float x, __nv_bfloat16& hi, __nv_bfloat16& lo) {
    hi = __float2bfloat16(x);
    lo = __float2bfloat16(x - __bfloat162float(hi));
}
// FAST split: two floats -> packed bf16x2 hi word + lo word (a low, b high).
__device__ __forceinline__ void split2(float a, float b, uint32_t& hw, uint32_t& lw) {
    asm("cvt.rn.bf16x2.f32 %0, %1, %2;" : "=r"(hw) : "f"(b), "f"(a));  // low=a, high=b
    float fa = __uint_as_float(hw << 16);
    float fb = __uint_as_float(hw & 0xffff0000u);
    asm("cvt.rn.bf16x2.f32 %0, %1, %2;" : "=r"(lw) : "f"(b - fb), "f"(a - fa));
}

// ---------------- K_init: lambda/x0/pack/P2 merged (grid 45 x 256) -----------
__global__ void k_init(const float* __restrict__ y0,
                       const float* __restrict__ lre,
                       const float* __restrict__ lim,
                       const float* __restrict__ B,
                       const float* __restrict__ Wy2x,
                       const float* __restrict__ by2x,
                       const float* __restrict__ Wx2y) {
    int blk = blockIdx.x, tid = threadIdx.x;
    if (blk == 0) {
        if (tid < HH) {
            int h = tid;
            float ar = fabsf(lre[h]);
            float th = 1.5707963267948966f * lim[h];
            float r  = expf(-ar);
            float sn, cs;
            sincosf(th, &sn, &cs);
            g_lam[h] = make_float2(r * cs, r * sn);
            float rL = expf(-32.0f * ar);
            float sL, cL;
            sincosf(32.0f * th, &sL, &cL);
            g_lamL[h] = make_float2(rL * cL, rL * sL);
        }
    } else if (blk <= 32) {
        __shared__ float ys[NY];
        int b = blk - 1;
        if (tid < NY) ys[tid] = y0[b * NY + tid];
        __syncthreads();
        int j = tid;
        float acc = by2x[j];
        #pragma unroll
        for (int y = 0; y < NY; y++) acc = fmaf(Wy2x[j * NY + y], ys[y], acc);
        g_x0[b * NH + j] = acc;
    } else if (blk <= 36) {
        __nv_bfloat16* bp = (__nv_bfloat16*)g_B1h;
        int base = (blk - 33) * 4096;
        for (int q = tid; q < 4096; q += 256) {
            int i = base + q;
            int h = i >> 6, u = i & 63;
            int hp = (h < HH) ? h : (h - HH);
            int n  = hp >> 6;
            int r  = (hp & 63) + ((h < HH) ? 0 : 64);
            __nv_bfloat16 hi, lo;
            split_bf16(B[i], hi, lo);
            __nv_bfloat16* dst = bp + n * (128 * 136);
            dst[r * 136 + u]      = hi;
            dst[r * 136 + 64 + u] = lo;
        }
    } else if (blk <= 40) {
        // W quarter pack
        __nv_bfloat16* wp = (__nv_bfloat16*)g_W4p;
        int base = (blk - 37) * 4096;
        for (int qq = tid; qq < 4096; qq += 256) {
            int i = base + qq;
            int y = i >> 8, k = i & 255;
            __nv_bfloat16 hi, lo;
            split_bf16(Wx2y[i], hi, lo);
            int hp  = (k < HH) ? k : (k - HH);
            int q   = hp >> 5;
            int col = (hp & 31) + ((k < HH) ? 0 : 32);
            __nv_bfloat16* dst = wp + q * (64 * 136) + y * 136;
            dst[col]      = hi;
            dst[col + 64] = lo;
        }
    } else {
        // P2 table, parallelized: blocks 41-44, each 8 k values x 128 h
        int k0 = (blk - 41) * 8;
        #pragma unroll
        for (int it = 0; it < 4; it++) {
            int e = it * 256 + tid;           // 0..1023
            int k = k0 + (e >> 7);
            int h = e & 127;
            float ar = fabsf(lre[h]);
            float th = 1.5707963267948966f * lim[h];
            float kk = (float)(k + 1);
            float rho = expf(-kk * ar);
            float s2, c2;
            sincosf(kk * th, &s2, &c2);
            g_P2[k * HH + h] = make_float2(rho * c2, rho * s2);
        }
    }
}

// ---------------- K_A: HMMA Bu GEMM (N-half) + 32-step scan ------------------
// grid (64, 32, 2): tile c (64 rows), batch b, channel-half n. 256 threads.
#define FA_A1 0
#define FA_B1 17408
#define FA_TOTAL 52224
#define XPITCH 65

__global__ __launch_bounds__(256, 3)
void k_fusedA(const float* __restrict__ U) {
    extern __shared__ char smem[];
    uint32_t sb = smem_u32(smem);
    int tid = threadIdx.x, wid = tid >> 5, lane = tid & 31;
    int c = blockIdx.x, b = blockIdx.y, n = blockIdx.z;
    int t0 = c * 64;

    // cp.async stage of B half (34816 B)
    {
        const char* src = (const char*)g_B1h + n * 34816;
        for (int i = tid; i < 2176; i += 256)
            cp16(sb + FA_B1 + i * 16, src + i * 16);
        CP_COMMIT();
    }
    // convert U tile -> A1 [tl=64][136] (hi | lo), vectorized float4 -> fast split2
    {
        __nv_bfloat16* ap = (__nv_bfloat16*)(smem + FA_A1);
        #pragma unroll
        for (int i = tid; i < 64 * 16; i += 256) {
            int tl = i >> 4, u4 = (i & 15) * 4;
            float4 v = *(const float4*)(U + ((size_t)(t0 + tl) * NB + b) * NU + u4);
            uint32_t hA, lA, hB, lB;
            split2(v.x, v.y, hA, lA);
            split2(v.z, v.w, hB, lB);
            *(uint2*)(ap + tl * 136 + u4)      = make_uint2(hA, hB);
            *(uint2*)(ap + tl * 136 + 64 + u4) = make_uint2(lA, lB);
        }
    }
    CP_WAIT0();
    __syncthreads();

    // GEMM: M=64, N=128(local), K=64 x 3 terms; warp = 16M x 64N.
    // Fragment-sharing loop order (R12 proven form).
    int wm = (wid & 3) * 16;
    int wn = (wid >> 2) * 64;
    int lr = lane & 15, lc = lane >> 4;
    uint32_t a_base = sb + FA_A1 + (uint32_t)(wm + lr) * 272u + (uint32_t)lc * 16u;
    uint32_t b_base = sb + FA_B1 + (uint32_t)(wn + lr) * 272u + (uint32_t)lc * 16u;

    float d[8][4];
    #pragma unroll
    for (int x = 0; x < 8; x++)
        #pragma unroll
        for (int q = 0; q < 4; q++) d[x][q] = 0.f;

    #pragma unroll
    for (int ks = 0; ks < 4; ks++) {
        uint32_t ah[4], al[4];
        ldsm4(ah, a_base + ks * 32u);           // A hi (cols 0..63)
        ldsm4(al, a_base + 128u + ks * 32u);    // A lo (cols 64..127)
        #pragma unroll
        for (int nt = 0; nt < 4; nt++) {
            uint32_t bh[4], bl[4];
            uint32_t boffn = ks * 32u + (uint32_t)nt * (16u * 272u);
            ldsm4(bh, b_base + boffn);          // B hi
            ldsm4(bl, b_base + 128u + boffn);   // B lo
            mma_bf16(d[2 * nt],     ah, bh[0], bh[2]);
            mma_bf16(d[2 * nt + 1], ah, bh[1], bh[3]);
            mma_bf16(d[2 * nt],     al, bh[0], bh[2]);
            mma_bf16(d[2 * nt + 1], al, bh[1], bh[3]);
            mma_bf16(d[2 * nt],     ah, bl[0], bl[2]);
            mma_bf16(d[2 * nt + 1], ah, bl[1], bl[3]);
        }
    }
    __syncthreads();   // done with A1/B1; reuse as Xs

    // transpose into Xs[hl=128][r=64 + pad]
    float* Xs = (float*)smem;
    {
        int g = lane >> 2, tq = lane & 3;
        #pragma unroll
        for (int dm = 0; dm < 8; dm++) {
            int hl = wn + dm * 8 + tq * 2;
            int r0 = wm + g;
            Xs[hl * XPITCH + r0]           = d[dm][0];
            Xs[(hl + 1) * XPITCH + r0]     = d[dm][1];
            Xs[hl * XPITCH + r0 + 8]       = d[dm][2];
            Xs[(hl + 1) * XPITCH + r0 + 8] = d[dm][3];
        }
    }
    __syncthreads();

    // 32-step scan: thread = (hp_loc, subchunk)
    if (tid < 128) {
        int hp = tid & 63, sc = tid >> 6;
        int hg = n * 64 + hp;
        float2 lam = g_lam[hg];
        const float* rowR = Xs + hp * XPITCH + sc * 32;
        const float* rowI = Xs + (64 + hp) * XPITCH + sc * 32;
        float zr = 0.f, zi = 0.f;
        #pragma unroll 4
        for (int k = 0; k < CH2; k++) {
            float a  = rowR[k];
            float bi = rowI[k];
            float nzr = fmaf(lam.x, zr, fmaf(-lam.y, zi, a));
            float nzi = fmaf(lam.y, zr, fmaf( lam.x, zi, bi));
            zr = nzr; zi = nzi;
            g_X2[((size_t)(t0 + sc * 32 + k) * NB + b) * HH + hg] = make_float2(zr, zi);
        }
        g_s[((c * 2 + sc) * NB + b) * HH + hg] = make_float2(zr, zi);
    }
}

// ---------------- K3: combine across 128 subchunks (prefetched) --------------
__global__ void k_combine() {
    int b = blockIdx.x;
    int h = threadIdx.x;
    float2 lamL = g_lamL[h];
    float Sr = g_x0[b * NH + h];
    float Si = g_x0[b * NH + HH + h];
    float2 buf[8];
    #pragma unroll
    for (int j = 0; j < 8; j++) buf[j] = g_s[(j * NB + b) * HH + h];
    #pragma unroll 1
    for (int c0 = 0; c0 < NC2; c0 += 8) {
        float2 nxt[8];
        if (c0 + 8 < NC2) {
            #pragma unroll
            for (int j = 0; j < 8; j++) nxt[j] = g_s[((c0 + 8 + j) * NB + b) * HH + h];
        }
        #pragma unroll
        for (int j = 0; j < 8; j++) {
            g_S[((c0 + j) * NB + b) * HH + h] = make_float2(Sr, Si);
            float2 s = buf[j];
            float nr = fmaf(lamL.x, Sr, fmaf(-lamL.y, Si, s.x));
            float ni = fmaf(lamL.y, Sr, fmaf( lamL.x, Si, s.y));
            Sr = nr; Si = ni;
        }
        #pragma unroll
        for (int j = 0; j < 8; j++) buf[j] = nxt[j];
    }
}

// ---------------- K_C: producer/consumer output GEMM -------------------------
// grid 2048 x 64 rows, 256 threads.
// warps 0-3: consumers (16x64 output tile each, term-outer order).
// warps 4-7: producers. K split in 4 quarters, double-buffered A2 + W.
#define OC_WBUF(i) (1024u + (uint32_t)(i) * 17408u)
#define OC_ABUF(i) (35840u + (uint32_t)(i) * 17408u)
#define OC_TOTAL 70656

__device__ __forceinline__ void oc_build_quarter(
        char* smem, int q, int abuf, int row0, int c2, int tl0,
        int wtid, int nthreads) {
    __nv_bfloat16* ap = (__nv_bfloat16*)(smem + OC_ABUF(abuf));
    #pragma unroll 4
    for (int idx = wtid; idx < 512; idx += nthreads) {
        int rp  = idx >> 4;            // row-pair 0..31 (b = rp)
        int jp  = (idx & 15) * 2;      // even local channel
        int hp  = q * 32 + jp;
        int R   = row0 + rp;
        float4 Sv  = *(const float4*)&g_S[(c2 * NB + rp) * HH + hp];
        float4 x0v = *(const float4*)&g_X2[(size_t)R * HH + hp];
        float4 x1v = *(const float4*)&g_X2[(size_t)(R + 32) * HH + hp];
        float4 P0  = *(const float4*)&g_P2[tl0 * HH + hp];
        float4 P1  = *(const float4*)&g_P2[(tl0 + 1) * HH + hp];
        float xr0a = fmaf(P0.x, Sv.x, fmaf(-P0.y, Sv.y, x0v.x));
        float xi0a = fmaf(P0.y, Sv.x, fmaf( P0.x, Sv.y, x0v.y));
        float xr0b = fmaf(P0.z, Sv.z, fmaf(-P0.w, Sv.w, x0v.z));
        float xi0b = fmaf(P0.w, Sv.z, fmaf( P0.z, Sv.w, x0v.w));
        float xr1a = fmaf(P1.x, Sv.x, fmaf(-P1.y, Sv.y, x1v.x));
        float xi1a = fmaf(P1.y, Sv.x, fmaf( P1.x, Sv.y, x1v.y));
        float xr1b = fmaf(P1.z, Sv.z, fmaf(-P1.w, Sv.w, x1v.z));
        float xi1b = fmaf(P1.w, Sv.z, fmaf( P1.z, Sv.w, x1v.w));
        uint32_t hR0, lR0, hI0, lI0, hR1, lR1, hI1, lI1;
        split2(xr0a, xr0b, hR0, lR0);
        split2(xi0a, xi0b, hI0, lI0);
        split2(xr1a, xr1b, hR1, lR1);
        split2(xi1a, xi1b, hI1, lI1);
        int wj = jp >> 1;              // word col 0..15 (row pitch 68 words)
        uint32_t* wA = (uint32_t*)(ap + (size_t)rp * 136);
        wA[wj]      = hR0;             // hi real  (cols 0..31)
        wA[16 + wj] = hI0;             // hi imag  (cols 32..63)
        wA[32 + wj] = lR0;             // lo real  (cols 64..95)
        wA[48 + wj] = lI0;             // lo imag  (cols 96..127)
        uint32_t* wB = (uint32_t*)(ap + (size_t)(rp + 32) * 136);
        wB[wj]      = hR1;
        wB[16 + wj] = hI1;
        wB[32 + wj] = lR1;
        wB[48 + wj] = lI1;
    }
}

__global__ __launch_bounds__(256, 3)
void k_outC(const float* __restrict__ bias, float* __restrict__ Y) {
    extern __shared__ char smem[];
    uint32_t sb = smem_u32(smem);
    int tid = threadIdx.x, wid = tid >> 5, lane = tid & 31;
    int row0 = blockIdx.x * 64;
    int t_base = blockIdx.x * 2;
    int c2 = t_base >> 5;
    int tl0 = t_base & 31;
    int lr = lane & 15, lc = lane >> 4;

    if (tid < NY) ((float*)smem)[tid] = bias[tid];

    float d[8][4];
    #pragma unroll
    for (int x = 0; x < 8; x++)
        #pragma unroll
        for (int qq = 0; qq < 4; qq++) d[x][qq] = 0.f;

    // prologue: ALL 256 threads stage quarter 0 (W + A2)
    {
        const char* src = (const char*)g_W4p;
        for (int i = tid; i < 1088; i += 256)
            cp16(sb + OC_WBUF(0) + i * 16, src + i * 16);
        CP_COMMIT();
        oc_build_quarter(smem, 0, 0, row0, c2, tl0, tid, 256);
        CP_WAIT0();
    }
    __syncthreads();

    #pragma unroll 1
    for (int q = 0; q < 4; q++) {
        int buf = q & 1, nbuf = buf ^ 1;
        if (wid >= 4) {
            if (q < 3) {
                int ptid = tid - 128;
                const char* src = (const char*)g_W4p + (q + 1) * 17408;
                for (int i = ptid; i < 1088; i += 128)
                    cp16(sb + OC_WBUF(nbuf) + i * 16, src + i * 16);
                CP_COMMIT();
                oc_build_quarter(smem, q + 1, nbuf, row0, c2, tl0, tid - 128, 128);
                CP_WAIT0();
            }
        } else {
            // consumer GEMM on quarter q: M=16 (this warp), N=64, K=64 x 3 terms.
            // R10 term-outer loop (measured best).
            uint32_t a_base = sb + OC_ABUF(buf) + (uint32_t)(wid * 16 + lr) * 272u
                            + (uint32_t)lc * 16u;
            uint32_t b_base = sb + OC_WBUF(buf) + (uint32_t)lr * 272u
                            + (uint32_t)lc * 16u;
            #pragma unroll
            for (int t = 0; t < 3; t++) {
                const uint32_t aoff = (t == 1) ? 128u : 0u;   // A-lo at +64 cols
                const uint32_t boff = (t == 2) ? 128u : 0u;   // W-lo at +64 cols
                #pragma unroll
                for (int ks = 0; ks < 4; ks++) {
                    uint32_t a[4];
                    ldsm4(a, a_base + aoff + ks * 32u);
                    #pragma unroll
                    for (int nt = 0; nt < 4; nt++) {
                        uint32_t bf[4];
                        ldsm4(bf, b_base + boff + ks * 32u + (uint32_t)nt * (16u * 272u));
                        mma_bf16(d[2 * nt],     a, bf[0], bf[2]);
                        mma_bf16(d[2 * nt + 1], a, bf[1], bf[3]);
                    }
                }
            }
        }
        __syncthreads();
    }

    // epilogue: consumers add bias + store
    if (wid < 4) {
        const float* bs = (const float*)smem;
        int g = lane >> 2, tq = lane & 3;
        int RA = row0 + wid * 16 + g;
        int RB = RA + 8;
        #pragma unroll
        for (int nt = 0; nt < 8; nt++) {
            int col = nt * 8 + tq * 2;
            float b0 = bs[col], b1 = bs[col + 1];
            *(float2*)(Y + (size_t)RA * NY + col) = make_float2(d[nt][0] + b0, d[nt][1] + b1);
            *(float2*)(Y + (size_t)RB * NY + col) = make_float2(d[nt][2] + b0, d[nt][3] + b1);
        }
    }
}

// ---------------- launch ----------------------------------------------------
extern "C" void kernel_launch(void* const* d_in, const int* in_sizes, int n_in,
                              void* d_out, int out_size) {
    const float* y0   = (const float*)d_in[0];
    const float* U    = (const float*)d_in[1];
    const float* lre  = (const float*)d_in[2];
    const float* lim  = (const float*)d_in[3];
    const float* B    = (const float*)d_in[4];
    const float* Wy2x = (const float*)d_in[5];
    const float* by2x = (const float*)d_in[6];
    const float* Wx2y = (const float*)d_in[7];
    const float* bx2y = (const float*)d_in[8];
    float* Y = (float*)d_out;

    k_init<<<45, 256>>>(y0, lre, lim, B, Wy2x, by2x, Wx2y);

    cudaFuncSetAttribute(k_fusedA, cudaFuncAttributeMaxDynamicSharedMemorySize, FA_TOTAL);
    k_fusedA<<<dim3(64, NB, 2), 256, FA_TOTAL>>>(U);

    k_combine<<<NB, 128>>>();

    cudaFuncSetAttribute(k_outC, cudaFuncAttributeMaxDynamicSharedMemorySize, OC_TOTAL);
    k_outC<<<NROWS / 64, 256, OC_TOTAL>>>(bx2y, Y);
}